// round 1
// baseline (speedup 1.0000x reference)
#include <cuda_runtime.h>
#include <cuda_bf16.h>
#include <cstdint>

// Problem constants
#define BB      32
#define SS      4096
#define DV      512
#define HH      256
#define NSPLIT  16
#define SCHUNK  (SS / NSPLIT)   // 256
#define TS      64              // s-tile rows per GEMM tile
#define KT      32              // K tile

// Scratch (allocation-free rule: __device__ globals)
__device__ float g_qb[BB * HH];                 // query@W2 + bias
__device__ float g_part[BB][NSPLIT][2 + DV];    // [m, sumexp, acc[512]] per split

// ---------------------------------------------------------------------------
// helpers
// ---------------------------------------------------------------------------
__device__ __forceinline__ uint32_t f2tf(float x) {
    uint32_t u;
    asm("cvt.rna.tf32.f32 %0, %1;" : "=r"(u) : "f"(x));
    return u;
}

__device__ __forceinline__ void mma_tf32(float c[4], const uint32_t a[4],
                                         uint32_t b0, uint32_t b1) {
    asm volatile(
        "mma.sync.aligned.m16n8k8.row.col.f32.tf32.tf32.f32 "
        "{%0,%1,%2,%3}, {%4,%5,%6,%7}, {%8,%9}, {%0,%1,%2,%3};\n"
        : "+f"(c[0]), "+f"(c[1]), "+f"(c[2]), "+f"(c[3])
        : "r"(a[0]), "r"(a[1]), "r"(a[2]), "r"(a[3]), "r"(b0), "r"(b1));
}

// ---------------------------------------------------------------------------
// Kernel A: qb[b][h] = sum_d query[b][d] * W2[d][h] + bias[h]
// ---------------------------------------------------------------------------
__global__ void qb_kernel(const float* __restrict__ enc,
                          const float* __restrict__ W2,
                          const float* __restrict__ bias) {
    int b = blockIdx.x;
    int h = threadIdx.x;           // 256
    __shared__ float q_s[512];
    q_s[h]       = enc[b * 512 + h];
    q_s[h + 256] = enc[b * 512 + 256 + h];
    __syncthreads();
    float acc = bias[h];
#pragma unroll 8
    for (int d = 0; d < 512; d++)
        acc += q_s[d] * W2[d * HH + h];
    g_qb[b * HH + h] = acc;
}

// ---------------------------------------------------------------------------
// Kernel B: main — per (split, batch) block:
//   for each 64-row s-tile (until len): GEMM(64x256, K=512) in tf32 mma,
//   fused tanh/dot-w epilogue -> scores, online softmax accumulate of context.
// ---------------------------------------------------------------------------
__global__ void __launch_bounds__(256, 2)
attn_main(const float* __restrict__ ctx,
          const int*   __restrict__ lens,
          const float* __restrict__ W1,
          const float* __restrict__ wv) {
    const int split = blockIdx.x;
    const int b     = blockIdx.y;
    const int tid   = threadIdx.x;
    const int lane  = tid & 31;
    const int wid   = tid >> 5;
    const int warp_m = wid >> 2;     // 0..1 (32 rows each)
    const int warp_n = wid & 3;      // 0..3 (64 cols each)

    const int s0  = split * SCHUNK;
    const int len = lens[b];

    __shared__ uint32_t As[KT * 68];     // A transposed [k][row], pad 68
    __shared__ uint32_t Bs[KT * 260];    // B [k][n], pad 260
    __shared__ float qb_s[HH], w_s[HH];
    __shared__ float sc[TS], ev[TS];
    __shared__ float m_run, sum_run, scale_s;

    qb_s[tid] = g_qb[b * HH + tid];
    w_s[tid]  = wv[tid];
    if (tid == 0) { m_run = -1e30f; sum_run = 0.f; }

    float2 acc = make_float2(0.f, 0.f);

    int nt = 0;
    if (len > s0) {
        int rem = len - s0;
        nt = (rem + TS - 1) / TS;
        if (nt > SCHUNK / TS) nt = SCHUNK / TS;
    }
    __syncthreads();

    for (int t = 0; t < nt; t++) {
        const int gs0 = s0 + t * TS;
        if (tid < TS) sc[tid] = 0.f;

        float c[2][8][4];
#pragma unroll
        for (int ma = 0; ma < 2; ma++)
#pragma unroll
            for (int na = 0; na < 8; na++)
#pragma unroll
                for (int e = 0; e < 4; e++) c[ma][na][e] = 0.f;

        const float* actx = ctx + ((size_t)b * SS + gs0) * DV;

#pragma unroll 1
        for (int kb = 0; kb < DV; kb += KT) {
            // load A tile (64 x 32) transposed into As[k][row], tf32
#pragma unroll
            for (int i = 0; i < 2; i++) {
                int fid = tid + i * 256;          // 0..511
                int row = fid >> 3;               // 0..63
                int q   = fid & 7;                // 0..7 (float4 within K tile)
                float4 v = *(const float4*)(actx + (size_t)row * DV + kb + q * 4);
                As[(q * 4 + 0) * 68 + row] = f2tf(v.x);
                As[(q * 4 + 1) * 68 + row] = f2tf(v.y);
                As[(q * 4 + 2) * 68 + row] = f2tf(v.z);
                As[(q * 4 + 3) * 68 + row] = f2tf(v.w);
            }
            // load B tile (32 x 256) into Bs[k][n], tf32
            const float* bptr = W1 + (size_t)kb * HH;
#pragma unroll
            for (int i = 0; i < 8; i++) {
                int fid = tid + i * 256;          // 0..2047
                int row = fid >> 6;               // 0..31
                int q   = fid & 63;               // 0..63 (float4 within row)
                float4 v = *(const float4*)(bptr + (size_t)row * HH + q * 4);
                Bs[row * 260 + q * 4 + 0] = f2tf(v.x);
                Bs[row * 260 + q * 4 + 1] = f2tf(v.y);
                Bs[row * 260 + q * 4 + 2] = f2tf(v.z);
                Bs[row * 260 + q * 4 + 3] = f2tf(v.w);
            }
            __syncthreads();

#pragma unroll
            for (int ks = 0; ks < KT; ks += 8) {
                uint32_t a[2][4];
#pragma unroll
                for (int ma = 0; ma < 2; ma++) {
                    int rb = warp_m * 32 + ma * 16;
                    int kc = ks + (lane & 3);
                    int g  = lane >> 2;
                    a[ma][0] = As[kc * 68 + rb + g];
                    a[ma][1] = As[kc * 68 + rb + 8 + g];
                    a[ma][2] = As[(kc + 4) * 68 + rb + g];
                    a[ma][3] = As[(kc + 4) * 68 + rb + 8 + g];
                }
#pragma unroll
                for (int na = 0; na < 8; na++) {
                    int nb = warp_n * 64 + na * 8 + (lane >> 2);
                    uint32_t b0 = Bs[(ks + (lane & 3)) * 260 + nb];
                    uint32_t b1 = Bs[(ks + 4 + (lane & 3)) * 260 + nb];
                    mma_tf32(c[0][na], a[0], b0, b1);
                    mma_tf32(c[1][na], a[1], b0, b1);
                }
            }
            __syncthreads();
        }

        // epilogue: score_row += sum_h tanh(c + qb[h]) * w[h]
#pragma unroll
        for (int ma = 0; ma < 2; ma++) {
            float p_lo = 0.f, p_hi = 0.f;
#pragma unroll
            for (int na = 0; na < 8; na++) {
                int col = warp_n * 64 + na * 8 + 2 * (lane & 3);
                float w0 = w_s[col],  w1 = w_s[col + 1];
                float q0 = qb_s[col], q1 = qb_s[col + 1];
                p_lo += tanhf(c[ma][na][0] + q0) * w0 + tanhf(c[ma][na][1] + q1) * w1;
                p_hi += tanhf(c[ma][na][2] + q0) * w0 + tanhf(c[ma][na][3] + q1) * w1;
            }
            p_lo += __shfl_xor_sync(0xffffffffu, p_lo, 1);
            p_lo += __shfl_xor_sync(0xffffffffu, p_lo, 2);
            p_hi += __shfl_xor_sync(0xffffffffu, p_hi, 1);
            p_hi += __shfl_xor_sync(0xffffffffu, p_hi, 2);
            if ((lane & 3) == 0) {
                int r = warp_m * 32 + ma * 16 + (lane >> 2);
                atomicAdd(&sc[r], p_lo);
                atomicAdd(&sc[r + 8], p_hi);
            }
        }
        __syncthreads();

        // online softmax update (warp 0)
        if (wid == 0) {
            float sv0 = sc[lane], sv1 = sc[lane + 32];
            if (gs0 + lane >= len)      sv0 = -1e30f;
            if (gs0 + lane + 32 >= len) sv1 = -1e30f;
            float mx = fmaxf(sv0, sv1);
#pragma unroll
            for (int o = 16; o; o >>= 1)
                mx = fmaxf(mx, __shfl_xor_sync(0xffffffffu, mx, o));
            float mo = m_run;
            float mn = fmaxf(mo, mx);
            float scl = expf(mo - mn);
            float e0 = expf(sv0 - mn), e1 = expf(sv1 - mn);
            ev[lane] = e0; ev[lane + 32] = e1;
            float es = e0 + e1;
#pragma unroll
            for (int o = 16; o; o >>= 1)
                es += __shfl_xor_sync(0xffffffffu, es, o);
            if (lane == 0) {
                sum_run = sum_run * scl + es;
                m_run   = mn;
                scale_s = scl;
            }
        }
        __syncthreads();

        // accumulate exp-weighted context rows (each thread owns 2 dims)
        float scl = scale_s;
        acc.x *= scl; acc.y *= scl;
        const float* crow = ctx + ((size_t)b * SS + gs0) * DV + 2 * tid;
#pragma unroll 4
        for (int si = 0; si < TS; si++) {
            float e = ev[si];
            if (e != 0.f) {
                float2 v = *(const float2*)(crow + (size_t)si * DV);
                acc.x += e * v.x;
                acc.y += e * v.y;
            }
        }
    }

    __syncthreads();
    float* gp = &g_part[b][split][0];
    if (tid == 0) { gp[0] = m_run; gp[1] = sum_run; }
    gp[2 + 2 * tid] = acc.x;
    gp[3 + 2 * tid] = acc.y;
}

// ---------------------------------------------------------------------------
// Kernel C: combine splits (log-sum-exp merge), normalize, write out (B, DV)
// ---------------------------------------------------------------------------
__global__ void combine_kernel(float* __restrict__ out) {
    int b = blockIdx.x;
    int tid = threadIdx.x;   // 256
    __shared__ float ms[NSPLIT], f[NSPLIT], den_s;

    if (tid < NSPLIT) ms[tid] = g_part[b][tid][0];
    __syncthreads();
    if (tid == 0) {
        float M = ms[0];
#pragma unroll
        for (int i = 1; i < NSPLIT; i++) M = fmaxf(M, ms[i]);
        float den = 0.f;
#pragma unroll
        for (int i = 0; i < NSPLIT; i++) {
            float fi = expf(ms[i] - M);
            f[i] = fi;
            den += fi * g_part[b][i][1];
        }
        den_s = den;
    }
    __syncthreads();

    float n0 = 0.f, n1 = 0.f;
#pragma unroll
    for (int i = 0; i < NSPLIT; i++) {
        float fi = f[i];
        if (fi != 0.f) {
            n0 += fi * g_part[b][i][2 + 2 * tid];
            n1 += fi * g_part[b][i][3 + 2 * tid];
        }
    }
    float inv = 1.f / den_s;
    ((float2*)out)[b * 256 + tid] = make_float2(n0 * inv, n1 * inv);
}

// ---------------------------------------------------------------------------
// launch
// ---------------------------------------------------------------------------
extern "C" void kernel_launch(void* const* d_in, const int* in_sizes, int n_in,
                              void* d_out, int out_size) {
    const float* enc  = (const float*)d_in[0];   // (1, B, DQ)
    const float* ctx  = (const float*)d_in[1];   // (B, S, DV)
    const int*   lens = (const int*)  d_in[2];   // (B,)
    const float* W1   = (const float*)d_in[3];   // (DV, H)
    const float* W2   = (const float*)d_in[4];   // (DQ, H)
    const float* bias = (const float*)d_in[5];   // (1, 1, H)
    const float* wv   = (const float*)d_in[6];   // (H, 1)
    float* out = (float*)d_out;                  // (B, DV)

    qb_kernel<<<BB, 256>>>(enc, W2, bias);
    attn_main<<<dim3(NSPLIT, BB), 256>>>(ctx, lens, W1, wv);
    combine_kernel<<<BB, 256>>>(out);
}

// round 3
// speedup vs baseline: 1.3706x; 1.3706x over previous
#include <cuda_runtime.h>
#include <cstdint>

// ---------------------------------------------------------------------------
// Problem constants
// ---------------------------------------------------------------------------
#define BB     32
#define SSEQ   4096
#define DV     512
#define HH     256
#define NSPLIT 16
#define SCHUNK 256            // S-rows per CTA
#define TS     128            // S-rows per GEMM tile (up to 2 tiles per CTA)
#define KT     32             // K chunk (floats)
#define NKC    16             // 512 / 32
#define NSTAGE 3

// Per-stage SMEM: A [128][36] floats, B [32][264] floats
#define A_STRIDE  36
#define B_STRIDE  264
#define A_BYTES   (TS * A_STRIDE * 4)             // 18432
#define B_OFF     A_BYTES
#define STAGE_SZ  (A_BYTES + KT * B_STRIDE * 4)   // 52224
#define SMEM_TOTAL (NSTAGE * STAGE_SZ)            // 156672

// ---------------------------------------------------------------------------
// Device scratch (allocation-free rule)
// ---------------------------------------------------------------------------
__device__ float g_qbp[8][BB][HH];               // partial query@W2
__device__ float g_part[BB][NSPLIT][2 + DV];     // m, sumexp, acc[512]

// ---------------------------------------------------------------------------
// helpers
// ---------------------------------------------------------------------------
__device__ __forceinline__ uint32_t f2tf(float x) {
    uint32_t u;
    asm("cvt.rna.tf32.f32 %0, %1;" : "=r"(u) : "f"(x));
    return u;
}

__device__ __forceinline__ void mma_tf32(float c[4], const uint32_t a[4],
                                         uint32_t b0, uint32_t b1) {
    asm volatile(
        "mma.sync.aligned.m16n8k8.row.col.f32.tf32.tf32.f32 "
        "{%0,%1,%2,%3}, {%4,%5,%6,%7}, {%8,%9}, {%0,%1,%2,%3};\n"
        : "+f"(c[0]), "+f"(c[1]), "+f"(c[2]), "+f"(c[3])
        : "r"(a[0]), "r"(a[1]), "r"(a[2]), "r"(a[3]), "r"(b0), "r"(b1));
}

__device__ __forceinline__ uint32_t smem_u32(const void* p) {
    uint32_t a;
    asm("{ .reg .u64 t; cvta.to.shared.u64 t, %1; cvt.u32.u64 %0, t; }"
        : "=r"(a) : "l"(p));
    return a;
}

__device__ __forceinline__ void cp16(uint32_t dst, const void* src) {
    asm volatile("cp.async.cg.shared.global [%0], [%1], 16;\n"
                 :: "r"(dst), "l"(src));
}
#define CP_COMMIT() asm volatile("cp.async.commit_group;\n" ::: "memory")
#define CP_WAIT(n)  asm volatile("cp.async.wait_group %0;\n" :: "n"(n) : "memory")

// ---------------------------------------------------------------------------
// qb partials: g_qbp[c][b][h] = sum_{d in chunk c} q[b][d] * W2[d][h]
// ---------------------------------------------------------------------------
__global__ void qbp_kernel(const float* __restrict__ enc,
                           const float* __restrict__ W2) {
    int b = blockIdx.x, c = blockIdx.y, h = threadIdx.x;
    const float* q = enc + b * DV + c * 64;
    const float* w = W2 + (size_t)(c * 64) * HH + h;
    float acc = 0.f;
#pragma unroll 16
    for (int d = 0; d < 64; d++)
        acc += __ldg(q + d) * __ldg(w + (size_t)d * HH);
    g_qbp[c][b][h] = acc;
}

// ---------------------------------------------------------------------------
// Main kernel
// ---------------------------------------------------------------------------
extern __shared__ __align__(128) char dsmem[];

__device__ __forceinline__ void load_chunk(uint32_t sb, int stage, int chunk,
                                           const float* __restrict__ ctx_tile,
                                           const float* __restrict__ W1,
                                           int tid) {
    const int kb = chunk * KT;
    const uint32_t aBase = sb + stage * STAGE_SZ;
    const uint32_t bBase = aBase + B_OFF;
    const float* gA = ctx_tile + kb;
    const float* gB = W1 + (size_t)kb * HH;
#pragma unroll
    for (int i = 0; i < 4; i++) {            // A: 128 rows x 8 float4
        int g = tid + i * 256;
        int row = g >> 3, q = g & 7;
        cp16(aBase + row * (A_STRIDE * 4) + q * 16,
             gA + (size_t)row * DV + q * 4);
    }
#pragma unroll
    for (int i = 0; i < 8; i++) {            // B: 32 k-rows x 64 float4
        int g = tid + i * 256;
        int row = g >> 6, q = g & 63;
        cp16(bBase + row * (B_STRIDE * 4) + q * 16,
             gB + (size_t)row * HH + q * 4);
    }
}

__global__ void __launch_bounds__(256, 1)
attn_main(const float* __restrict__ ctx,
          const int*   __restrict__ lens,
          const float* __restrict__ W1,
          const float* __restrict__ bias,
          const float* __restrict__ wv) {
    const int split = blockIdx.x;
    const int b     = blockIdx.y;
    const int tid   = threadIdx.x;
    const int lane  = tid & 31;
    const int wid   = tid >> 5;
    const int warp_m = wid >> 1;        // 0..3 (32 rows each)
    const int warp_n = wid & 1;         // 0..1 (128 cols each)
    const int g = lane >> 2;            // 0..7
    const int t = lane & 3;             // 0..3

    const int s0  = split * SCHUNK;
    const int len = lens[b];

    float* gp = &g_part[b][split][0];
    if (len <= s0) {                    // inactive split: neutral partial
        if (tid == 0) { gp[0] = -1e30f; gp[1] = 0.f; }
        gp[2 + 2 * tid] = 0.f;
        gp[3 + 2 * tid] = 0.f;
        return;
    }

    const uint32_t sb = smem_u32(dsmem);

    __shared__ float qb_s[HH], w_s[HH];
    __shared__ float sc[TS], ev[TS];
    __shared__ float m_run, sum_run, scale_s;

    {
        float q = bias[tid];
#pragma unroll
        for (int c = 0; c < 8; c++) q += g_qbp[c][b][tid];
        qb_s[tid] = q;
        w_s[tid]  = wv[tid];
    }
    if (tid == 0) { m_run = -1e30f; sum_run = 0.f; }

    const int rem = len - s0;
    const int nt  = (rem > TS) ? 2 : 1;
    float acc_x = 0.f, acc_y = 0.f;
    __syncthreads();

    for (int tile = 0; tile < nt; tile++) {
        const int gs0 = s0 + tile * TS;
        const int nv  = min(TS, len - gs0);
        const float* ctx_tile = ctx + ((size_t)b * SSEQ + gs0) * DV;

        if (tid < TS) sc[tid] = 0.f;

        float c[2][16][4];
#pragma unroll
        for (int mf = 0; mf < 2; mf++)
#pragma unroll
            for (int na = 0; na < 16; na++)
#pragma unroll
                for (int e = 0; e < 4; e++) c[mf][na][e] = 0.f;

        // pipeline prologue: chunks 0, 1
        load_chunk(sb, 0, 0, ctx_tile, W1, tid); CP_COMMIT();
        load_chunk(sb, 1, 1, ctx_tile, W1, tid); CP_COMMIT();

#pragma unroll 1
        for (int kc = 0; kc < NKC; kc++) {
            CP_WAIT(1);
            __syncthreads();

            if (kc + 2 < NKC)
                load_chunk(sb, (kc + 2) % NSTAGE, kc + 2, ctx_tile, W1, tid);
            CP_COMMIT();   // uniform group counting even when empty

            const float* As = (const float*)(dsmem + (kc % NSTAGE) * STAGE_SZ);
            const float* Bs = (const float*)(dsmem + (kc % NSTAGE) * STAGE_SZ + B_OFF);

#pragma unroll
            for (int ks = 0; ks < KT; ks += 8) {
                uint32_t a[2][4];
#pragma unroll
                for (int mf = 0; mf < 2; mf++) {
                    const int rb = warp_m * 32 + mf * 16;
                    a[mf][0] = f2tf(As[(rb + g)     * A_STRIDE + ks + t]);
                    a[mf][1] = f2tf(As[(rb + 8 + g) * A_STRIDE + ks + t]);
                    a[mf][2] = f2tf(As[(rb + g)     * A_STRIDE + ks + 4 + t]);
                    a[mf][3] = f2tf(As[(rb + 8 + g) * A_STRIDE + ks + 4 + t]);
                }
#pragma unroll
                for (int na = 0; na < 16; na++) {
                    const int n0 = warp_n * 128 + na * 8 + g;
                    uint32_t b0 = f2tf(Bs[(ks + t)     * B_STRIDE + n0]);
                    uint32_t b1 = f2tf(Bs[(ks + 4 + t) * B_STRIDE + n0]);
                    mma_tf32(c[0][na], a[0], b0, b1);
                    mma_tf32(c[1][na], a[1], b0, b1);
                }
            }
            __syncthreads();   // all warps done with buffer before refill
        }

        // ---- epilogue: score_row += sum_h tanh(c + qb[h]) * w[h] ----
#pragma unroll
        for (int mf = 0; mf < 2; mf++) {
            float p_lo = 0.f, p_hi = 0.f;
#pragma unroll
            for (int na = 0; na < 16; na++) {
                const int col = warp_n * 128 + na * 8 + 2 * t;
                const float w0 = w_s[col],  w1 = w_s[col + 1];
                const float q0 = qb_s[col], q1 = qb_s[col + 1];
                p_lo += tanhf(c[mf][na][0] + q0) * w0 + tanhf(c[mf][na][1] + q1) * w1;
                p_hi += tanhf(c[mf][na][2] + q0) * w0 + tanhf(c[mf][na][3] + q1) * w1;
            }
            p_lo += __shfl_xor_sync(0xffffffffu, p_lo, 1);
            p_lo += __shfl_xor_sync(0xffffffffu, p_lo, 2);
            p_hi += __shfl_xor_sync(0xffffffffu, p_hi, 1);
            p_hi += __shfl_xor_sync(0xffffffffu, p_hi, 2);
            if (t == 0) {
                const int r = warp_m * 32 + mf * 16 + g;
                atomicAdd(&sc[r], p_lo);
                atomicAdd(&sc[r + 8], p_hi);
            }
        }
        __syncthreads();

        // ---- online softmax update (warp 0) ----
        if (wid == 0) {
            float sv[4];
            float mx = -1e30f;
#pragma unroll
            for (int j = 0; j < 4; j++) {
                const int r = lane + 32 * j;
                float v = (r < nv) ? sc[r] : -1e30f;
                sv[j] = v;
                mx = fmaxf(mx, v);
            }
#pragma unroll
            for (int o = 16; o; o >>= 1)
                mx = fmaxf(mx, __shfl_xor_sync(0xffffffffu, mx, o));
            const float mo = m_run;
            const float mn = fmaxf(mo, mx);
            const float scl = expf(mo - mn);
            float es = 0.f;
#pragma unroll
            for (int j = 0; j < 4; j++) {
                const int r = lane + 32 * j;
                float e = (r < nv) ? expf(sv[j] - mn) : 0.f;
                ev[r] = e;
                es += e;
            }
#pragma unroll
            for (int o = 16; o; o >>= 1)
                es += __shfl_xor_sync(0xffffffffu, es, o);
            if (lane == 0) {
                sum_run = sum_run * scl + es;
                m_run   = mn;
                scale_s = scl;
            }
        }
        __syncthreads();

        // ---- weighted context accumulation (thread owns 2 dims) ----
        {
            const float scl = scale_s;
            acc_x *= scl; acc_y *= scl;
            const float* cr = ctx_tile + 2 * tid;
#pragma unroll 4
            for (int r = 0; r < nv; r++) {
                const float e = ev[r];
                const float2 v = *(const float2*)(cr + (size_t)r * DV);
                acc_x += e * v.x;
                acc_y += e * v.y;
            }
        }
    }

    __syncthreads();
    gp[2 + 2 * tid] = acc_x;
    gp[3 + 2 * tid] = acc_y;
    if (tid == 0) { gp[0] = m_run; gp[1] = sum_run; }
}

// ---------------------------------------------------------------------------
// Combine splits (log-sum-exp merge), normalize, write out (B, DV)
// ---------------------------------------------------------------------------
__global__ void combine_kernel(float* __restrict__ out) {
    int b = blockIdx.x;
    int tid = threadIdx.x;
    __shared__ float ms[NSPLIT], f[NSPLIT], den_s;

    if (tid < NSPLIT) ms[tid] = g_part[b][tid][0];
    __syncthreads();
    if (tid == 0) {
        float M = ms[0];
#pragma unroll
        for (int i = 1; i < NSPLIT; i++) M = fmaxf(M, ms[i]);
        float den = 0.f;
#pragma unroll
        for (int i = 0; i < NSPLIT; i++) {
            float fi = expf(ms[i] - M);
            f[i] = fi;
            den += fi * g_part[b][i][1];
        }
        den_s = den;
    }
    __syncthreads();

    float n0 = 0.f, n1 = 0.f;
#pragma unroll
    for (int i = 0; i < NSPLIT; i++) {
        float fi = f[i];
        if (fi != 0.f) {
            n0 += fi * g_part[b][i][2 + 2 * tid];
            n1 += fi * g_part[b][i][3 + 2 * tid];
        }
    }
    float inv = 1.f / den_s;
    ((float2*)out)[b * 256 + tid] = make_float2(n0 * inv, n1 * inv);
}

// ---------------------------------------------------------------------------
// launch
// ---------------------------------------------------------------------------
extern "C" void kernel_launch(void* const* d_in, const int* in_sizes, int n_in,
                              void* d_out, int out_size) {
    const float* enc  = (const float*)d_in[0];   // (1, B, DQ)
    const float* ctx  = (const float*)d_in[1];   // (B, S, DV)
    const int*   lens = (const int*)  d_in[2];   // (B,)
    const float* W1   = (const float*)d_in[3];   // (DV, H)
    const float* W2   = (const float*)d_in[4];   // (DQ, H)
    const float* bias = (const float*)d_in[5];   // (1, 1, H)
    const float* wv   = (const float*)d_in[6];   // (H, 1)
    float* out = (float*)d_out;                  // (B, DV)

    cudaFuncSetAttribute(attn_main, cudaFuncAttributeMaxDynamicSharedMemorySize,
                         SMEM_TOTAL);

    qbp_kernel<<<dim3(BB, 8), 256>>>(enc, W2);
    attn_main<<<dim3(NSPLIT, BB), 256, SMEM_TOTAL>>>(ctx, lens, W1, bias, wv);
    combine_kernel<<<BB, 256>>>(out);
}